// round 11
// baseline (speedup 1.0000x reference)
#include <cuda_runtime.h>
#include <cuda_bf16.h>
#include <stdint.h>

#define BATCH 16
#define LQ    512
#define LK    4096
#define DM    128

#define TWO_LOG2E 2.8853900817779268f
#define Z_SCALE   1.2751743093739637f

typedef unsigned long long ull;

// ---------------- device scratch (no allocation allowed) ----------------
__device__ __align__(16) __nv_bfloat16 g_qh[(size_t)BATCH * LQ * DM];
__device__ __align__(16) __nv_bfloat16 g_ql[(size_t)BATCH * LQ * DM];
__device__ __align__(16) __nv_bfloat16 g_kh[(size_t)BATCH * LK * DM];
__device__ __align__(16) __nv_bfloat16 g_kl[(size_t)BATCH * LK * DM];

// ---------------- PTX helpers (baseline sm_80+ features only) ----------------
__device__ __forceinline__ uint32_t smem_u32(const void* p) {
    uint32_t a;
    asm("{ .reg .u64 t; cvta.to.shared.u64 t, %1; cvt.u32.u64 %0, t; }"
        : "=r"(a) : "l"(p));
    return a;
}
__device__ __forceinline__ void cp16(uint32_t dst, const void* src) {
    asm volatile("cp.async.cg.shared.global [%0], [%1], 16;"
                 :: "r"(dst), "l"(src) : "memory");
}
#define CP_COMMIT() asm volatile("cp.async.commit_group;" ::: "memory")
#define CP_WAIT0()  asm volatile("cp.async.wait_group 0;" ::: "memory")
#define CP_WAIT1()  asm volatile("cp.async.wait_group 1;" ::: "memory")

__device__ __forceinline__ void ldsm4(uint32_t& r0, uint32_t& r1,
                                      uint32_t& r2, uint32_t& r3, uint32_t a) {
    asm volatile("ldmatrix.sync.aligned.m8n8.x4.shared.b16 {%0,%1,%2,%3}, [%4];"
                 : "=r"(r0), "=r"(r1), "=r"(r2), "=r"(r3) : "r"(a));
}
__device__ __forceinline__ void mma_bf16(float* d, const uint32_t* a,
                                         const uint32_t* b) {
    asm volatile(
        "mma.sync.aligned.m16n8k16.row.col.f32.bf16.bf16.f32 "
        "{%0,%1,%2,%3}, {%4,%5,%6,%7}, {%8,%9}, {%0,%1,%2,%3};"
        : "+f"(d[0]), "+f"(d[1]), "+f"(d[2]), "+f"(d[3])
        : "r"(a[0]), "r"(a[1]), "r"(a[2]), "r"(a[3]), "r"(b[0]), "r"(b[1]));
}

// ---------------- packed f32x2 math (MUFU-free transcendentals) ----------------
__device__ __forceinline__ ull fma2v(ull a, ull b, ull c) {
    ull d; asm("fma.rn.f32x2 %0, %1, %2, %3;" : "=l"(d) : "l"(a), "l"(b), "l"(c));
    return d;
}
__device__ __forceinline__ ull mul2v(ull a, ull b) {
    ull d; asm("mul.rn.f32x2 %0, %1, %2;" : "=l"(d) : "l"(a), "l"(b)); return d;
}
__device__ __forceinline__ ull add2v(ull a, ull b) {
    ull d; asm("add.rn.f32x2 %0, %1, %2;" : "=l"(d) : "l"(a), "l"(b)); return d;
}
__device__ __forceinline__ float2 unpack2(ull u) {
    float2 f; asm("mov.b64 {%0, %1}, %2;" : "=f"(f.x), "=f"(f.y) : "l"(u)); return f;
}
__device__ __forceinline__ ull pack2(float a, float b) {
    ull u; asm("mov.b64 %0, {%1, %2};" : "=l"(u) : "f"(a), "f"(b)); return u;
}
__device__ __forceinline__ ull make2(float v) {
    unsigned u = __float_as_uint(v);
    return ((ull)u << 32) | (ull)u;
}

__device__ __forceinline__ ull exp2_2(ull y2) {
    ull t2 = add2v(y2, make2(12582912.0f));
    float2 t = unpack2(t2);
    int e0 = (__float_as_int(t.x) - 0x4B400000) << 23;
    int e1 = (__float_as_int(t.y) - 0x4B400000) << 23;
    ull tm2 = add2v(t2, make2(-12582912.0f));
    ull f2  = fma2v(tm2, make2(-1.0f), y2);
    ull p2  = make2(1.3333558146e-3f);
    p2 = fma2v(p2, f2, make2(9.6181291076e-3f));
    p2 = fma2v(p2, f2, make2(5.5504108664e-2f));
    p2 = fma2v(p2, f2, make2(2.4022650696e-1f));
    p2 = fma2v(p2, f2, make2(6.9314718056e-1f));
    p2 = fma2v(p2, f2, make2(1.0f));
    float2 p = unpack2(p2);
    return pack2(__int_as_float(__float_as_int(p.x) + e0),
                 __int_as_float(__float_as_int(p.y) + e1));
}
__device__ __forceinline__ ull rcp2(ull a2) {
    float2 a = unpack2(a2);
    float x0 = __int_as_float(0x7EF311C3 - __float_as_int(a.x));
    float x1 = __int_as_float(0x7EF311C3 - __float_as_int(a.y));
    ull x2  = pack2(x0, x1);
    ull na2 = mul2v(a2, make2(-1.0f));
    ull e2;
    e2 = fma2v(na2, x2, make2(2.0f)); x2 = mul2v(x2, e2);
    e2 = fma2v(na2, x2, make2(2.0f)); x2 = mul2v(x2, e2);
    e2 = fma2v(na2, x2, make2(2.0f)); x2 = mul2v(x2, e2);
    return x2;
}
// exp(C*tanh(s)) for two scores:  tanh(s) = 1 - 2/(1 + 2^{2 log2e s})
__device__ __forceinline__ ull attn_weight2(float s0, float s1) {
    float y0 = fminf(fmaxf(TWO_LOG2E * s0, -30.0f), 30.0f);
    float y1 = fminf(fmaxf(TWO_LOG2E * s1, -30.0f), 30.0f);
    ull u2 = exp2_2(pack2(y0, y1));
    ull r2 = rcp2(add2v(u2, make2(1.0f)));
    ull t2 = fma2v(r2, make2(-2.0f), make2(1.0f));
    return exp2_2(mul2v(t2, make2(Z_SCALE)));
}
__device__ __forceinline__ float fast_rcp(float a) {
    float x = __int_as_float(0x7EF311C3 - __float_as_int(a));
    x = x * fmaf(-a, x, 2.0f);
    x = x * fmaf(-a, x, 2.0f);
    x = x * fmaf(-a, x, 2.0f);
    return x;
}

// ---------------------------------------------------------------------------
// Merged projection, packed f32x2; writes bf16 hi/lo split arrays.
// ---------------------------------------------------------------------------
__global__ __launch_bounds__(256)
void proj_kernel(const float* __restrict__ Q, const float* __restrict__ Wq,
                 const float* __restrict__ bq,
                 const float* __restrict__ K, const float* __restrict__ Wk,
                 const float* __restrict__ bk)
{
    const bool is_q = blockIdx.x < (BATCH * LQ) / 64;
    const float* __restrict__ X    = is_q ? Q  : K;
    const float* __restrict__ W    = is_q ? Wq : Wk;
    const float* __restrict__ bias = is_q ? bq : bk;
    __nv_bfloat16* __restrict__ Yh = is_q ? g_qh : g_kh;
    __nv_bfloat16* __restrict__ Yl = is_q ? g_ql : g_kl;
    const int m0 = (is_q ? blockIdx.x : blockIdx.x - (BATCH * LQ) / 64) * 64;

    __shared__ __align__(16) float Xs[64 * 132];
    const int tid = threadIdx.x;

#pragma unroll
    for (int i = 0; i < 8; ++i) {
        int idx = tid + i * 256;
        int m   = idx >> 5;
        int d4  = idx & 31;
        float4 v = *(const float4*)(X + (size_t)(m0 + m) * DM + d4 * 4);
        *(float4*)(Xs + m * 132 + d4 * 4) = v;
    }
    __syncthreads();

    const int tx = tid & 15;
    const int ty = tid >> 4;
    const int c0 = tx * 8;

    ull acc[4][4];
#pragma unroll
    for (int r = 0; r < 4; ++r)
#pragma unroll
        for (int p = 0; p < 4; ++p) acc[r][p] = 0ull;

    for (int d4 = 0; d4 < 32; ++d4) {
        const int d = d4 * 4;
        ulonglong2 wv[4][2];
#pragma unroll
        for (int j = 0; j < 4; ++j) {
            const ulonglong2* wp =
                (const ulonglong2*)(W + (size_t)(d + j) * DM + c0);
            wv[j][0] = wp[0];
            wv[j][1] = wp[1];
        }
#pragma unroll
        for (int r = 0; r < 4; ++r) {
            float4 x4 = *(const float4*)(Xs + (ty * 4 + r) * 132 + d);
            float xv[4] = {x4.x, x4.y, x4.z, x4.w};
#pragma unroll
            for (int j = 0; j < 4; ++j) {
                ull xb = pack2(xv[j], xv[j]);
                acc[r][0] = fma2v(xb, wv[j][0].x, acc[r][0]);
                acc[r][1] = fma2v(xb, wv[j][0].y, acc[r][1]);
                acc[r][2] = fma2v(xb, wv[j][1].x, acc[r][2]);
                acc[r][3] = fma2v(xb, wv[j][1].y, acc[r][3]);
            }
        }
    }

    const ull* bp = (const ull*)(bias + c0);
    ull bb[4] = {bp[0], bp[1], bp[2], bp[3]};
#pragma unroll
    for (int r = 0; r < 4; ++r) {
        size_t row = (size_t)(m0 + ty * 4 + r) * DM;
        union { __nv_bfloat16 h[8]; uint4 v; } uh, ul;
#pragma unroll
        for (int p = 0; p < 4; ++p) {
            float2 a = unpack2(add2v(acc[r][p], bb[p]));
            __nv_bfloat16 h0 = __float2bfloat16_rn(a.x);
            __nv_bfloat16 h1 = __float2bfloat16_rn(a.y);
            uh.h[2 * p]     = h0;
            uh.h[2 * p + 1] = h1;
            ul.h[2 * p]     = __float2bfloat16_rn(a.x - __bfloat162float(h0));
            ul.h[2 * p + 1] = __float2bfloat16_rn(a.y - __bfloat162float(h1));
        }
        *(uint4*)(Yh + row + c0) = uh.v;
        *(uint4*)(Yl + row + c0) = ul.v;
    }
}

// ---------------------------------------------------------------------------
// Attention: mma.sync bf16 3-split, CTA = 64q x FULL 4096k, 512 threads
// (16 warps: 4 q-warps x 4 k-warps, warp tile 16q x 32k).
// 32 k-tiles of 128 tokens, THREE-stage cp.async pipeline (wait_group 1),
// mask prefetched before the MMA loop, CTA-local row sums + in-CTA normalize.
// smem: Q hi/lo @0/16384; K bufs @32768 + buf*65536 (hi @+0, lo @+32768).
// ---------------------------------------------------------------------------
#define SMQ   32768
#define KBUF  65536
#define SM_TOTAL (SMQ + 3 * KBUF)   // 229376 bytes

__global__ __launch_bounds__(512, 1)
void attn_kernel(const int* __restrict__ mask, float* __restrict__ out)
{
    extern __shared__ __align__(1024) char smem[];
    __shared__ float rsum[64];
    const uint32_t su = smem_u32(smem);
    const int tid  = threadIdx.x;
    const int wid  = tid >> 5;
    const int lane = tid & 31;
    const int q0   = blockIdx.x * 64;
    const int b    = blockIdx.y;

    const __nv_bfloat16* kh_base = g_kh + (size_t)b * LK * DM;
    const __nv_bfloat16* kl_base = g_kl + (size_t)b * LK * DM;

    // ---- stage Q + K tile 0 (group 0), K tile 1 (group 1) ----
    {
        const __nv_bfloat16* qh = g_qh + ((size_t)b * LQ + q0) * DM;
        const __nv_bfloat16* ql = g_ql + ((size_t)b * LQ + q0) * DM;
#pragma unroll
        for (int i = 0; i < 2; ++i) {
            int idx = tid + i * 512;        // 1024 16B chunks
            int row = idx >> 4, c = idx & 15;
            uint32_t d = (uint32_t)(row * 256 + ((c ^ (row & 7)) << 4));
            cp16(su + d,         qh + idx * 8);
            cp16(su + 16384 + d, ql + idx * 8);
        }
#pragma unroll
        for (int i = 0; i < 4; ++i) {
            int idx = tid + i * 512;        // 2048 16B chunks
            int row = idx >> 4, c = idx & 15;
            uint32_t d = (uint32_t)(row * 256 + ((c ^ (row & 7)) << 4));
            cp16(su + SMQ + d,         kh_base + idx * 8);
            cp16(su + SMQ + 32768 + d, kl_base + idx * 8);
        }
        CP_COMMIT();
#pragma unroll
        for (int i = 0; i < 4; ++i) {
            int idx = tid + i * 512;
            int row = idx >> 4, c = idx & 15;
            uint32_t d = (uint32_t)(row * 256 + ((c ^ (row & 7)) << 4));
            cp16(su + SMQ + KBUF + d,         kh_base + (128 * DM) + idx * 8);
            cp16(su + SMQ + KBUF + 32768 + d, kl_base + (128 * DM) + idx * 8);
        }
        CP_COMMIT();
    }
    if (tid < 64) rsum[tid] = 0.0f;

    // warp tiling: 4 q-warps (16 rows) x 4 k-warps (32 cols)
    const int q_off = (wid & 3) * 16;
    const int n_off = (wid >> 2) * 32;
    const int rsw   = lane & 7;
    const uint32_t aOff = (uint32_t)((q_off + (lane & 15)) * 256);
    const int aSel = (lane >> 4) & 1;
    const uint32_t bOff0 =
        (uint32_t)((n_off + ((lane >> 4) & 1) * 8 + (lane & 7)) * 256);
    const uint32_t bOff1 = bOff0 + 16 * 256;
    const int bSel = (lane >> 3) & 1;
    const int g   = lane >> 2;
    const int tig = lane & 3;

    const size_t rbase = ((size_t)(b * LQ + q0 + q_off + g)) * LK;
    float rs0 = 0.0f, rs1 = 0.0f;

    for (int t = 0; t < 32; ++t) {
        if (t < 31) { CP_WAIT1(); } else { CP_WAIT0(); }
        __syncthreads();

        // prefetch tile t+2 into buf (t+2)%3 (overwrites tile t-1's buffer,
        // whose readers all passed the sync above)
        if (t < 30) {
            const __nv_bfloat16* kh = kh_base + (size_t)(t + 2) * 128 * DM;
            const __nv_bfloat16* kl = kl_base + (size_t)(t + 2) * 128 * DM;
            uint32_t base = su + SMQ + (uint32_t)(((t + 2) % 3) * KBUF);
#pragma unroll
            for (int i = 0; i < 4; ++i) {
                int idx = tid + i * 512;
                int row = idx >> 4, c = idx & 15;
                uint32_t d = (uint32_t)(row * 256 + ((c ^ (row & 7)) << 4));
                cp16(base + d,         kh + idx * 8);
                cp16(base + 32768 + d, kl + idx * 8);
            }
            CP_COMMIT();
        }

        // prefetch this tile's mask values (overlaps the MMA loop)
        const int nb = t * 128 + n_off + 2 * tig;
        int2 mk[4][2];
#pragma unroll
        for (int j = 0; j < 4; ++j) {
            mk[j][0] = __ldg((const int2*)(mask + rbase + nb + 8 * j));
            mk[j][1] = __ldg((const int2*)(mask + rbase + (size_t)8 * LK
                                           + nb + 8 * j));
        }

        const uint32_t kbuf = su + SMQ + (uint32_t)((t % 3) * KBUF);

        float acc[4][4];
#pragma unroll
        for (int j = 0; j < 4; ++j)
#pragma unroll
            for (int v = 0; v < 4; ++v) acc[j][v] = 0.0f;

#pragma unroll 2
        for (int dc = 0; dc < 8; ++dc) {
            uint32_t ah[4], al[4], bh[4][2], bl[4][2];
            const uint32_t ca = (uint32_t)(((dc * 2 + aSel) ^ rsw) << 4);
            ldsm4(ah[0], ah[1], ah[2], ah[3], su + aOff + ca);
            ldsm4(al[0], al[1], al[2], al[3], su + 16384 + aOff + ca);
            const uint32_t cb = (uint32_t)(((dc * 2 + bSel) ^ rsw) << 4);
            ldsm4(bh[0][0], bh[0][1], bh[1][0], bh[1][1], kbuf + bOff0 + cb);
            ldsm4(bh[2][0], bh[2][1], bh[3][0], bh[3][1], kbuf + bOff1 + cb);
            ldsm4(bl[0][0], bl[0][1], bl[1][0], bl[1][1],
                  kbuf + 32768 + bOff0 + cb);
            ldsm4(bl[2][0], bl[2][1], bl[3][0], bl[3][1],
                  kbuf + 32768 + bOff1 + cb);
#pragma unroll
            for (int j = 0; j < 4; ++j) {
                mma_bf16(acc[j], ah, bh[j]);   // hi*hi
                mma_bf16(acc[j], ah, bl[j]);   // hi*lo
                mma_bf16(acc[j], al, bh[j]);   // lo*hi
            }
        }

        // ---- epilogue: weights, mask, store e, register row sums ----
#pragma unroll
        for (int j = 0; j < 4; ++j) {
            size_t i0 = rbase + (size_t)(nb + 8 * j);
            size_t i1 = i0 + (size_t)8 * LK;
            float2 w01 = unpack2(attn_weight2(acc[j][0], acc[j][1]));
            float2 w23 = unpack2(attn_weight2(acc[j][2], acc[j][3]));
            float e0 = mk[j][0].x ? w01.x : 0.0f;
            float e1 = mk[j][0].y ? w01.y : 0.0f;
            float e2 = mk[j][1].x ? w23.x : 0.0f;
            float e3 = mk[j][1].y ? w23.y : 0.0f;
            *(float2*)(out + i0) = make_float2(e0, e1);
            *(float2*)(out + i1) = make_float2(e2, e3);
            rs0 += e0 + e1;
            rs1 += e2 + e3;
        }
    }

    // ---- row sums: quad-reduce then smem atomicAdd (CTA-local) ----
    rs0 += __shfl_xor_sync(0xffffffffu, rs0, 1);
    rs0 += __shfl_xor_sync(0xffffffffu, rs0, 2);
    rs1 += __shfl_xor_sync(0xffffffffu, rs1, 1);
    rs1 += __shfl_xor_sync(0xffffffffu, rs1, 2);
    if (tig == 0) {
        atomicAdd(&rsum[q_off + g], rs0);
        atomicAdd(&rsum[q_off + 8 + g], rs1);
    }
    __syncthreads();

    // ---- normalize own rows (just-written -> L2-hot) ----
#pragma unroll
    for (int r = 0; r < 4; ++r) {
        int row = wid * 4 + r;
        float inv = fast_rcp(rsum[row]);
        float4* rowp = (float4*)(out + ((size_t)(b * LQ) + q0 + row) * LK);
#pragma unroll 8
        for (int it = 0; it < 32; ++it) {
            int idx = lane + it * 32;
            float4 v = rowp[idx];
            v.x *= inv; v.y *= inv; v.z *= inv; v.w *= inv;
            rowp[idx] = v;
        }
    }
}

// ---------------------------------------------------------------------------
// launch
// ---------------------------------------------------------------------------
extern "C" void kernel_launch(void* const* d_in, const int* in_sizes, int n_in,
                              void* d_out, int out_size)
{
    (void)in_sizes; (void)n_in; (void)out_size;
    const float* query = (const float*)d_in[0];
    const float* key   = (const float*)d_in[1];
    const int*   mask  = (const int*)  d_in[2];
    const float* Wq    = (const float*)d_in[3];
    const float* bq    = (const float*)d_in[4];
    const float* Wk    = (const float*)d_in[5];
    const float* bk    = (const float*)d_in[6];
    float* out = (float*)d_out;

    cudaFuncSetAttribute(attn_kernel,
                         cudaFuncAttributeMaxDynamicSharedMemorySize, SM_TOTAL);

    proj_kernel<<<(BATCH * LQ) / 64 + (BATCH * LK) / 64, 256>>>(
        query, Wq, bq, key, Wk, bk);

    dim3 grid(LQ / 64, BATCH);
    attn_kernel<<<grid, 512, SM_TOTAL>>>(mask, out);
}

// round 13
// speedup vs baseline: 1.2617x; 1.2617x over previous
#include <cuda_runtime.h>
#include <cuda_bf16.h>
#include <stdint.h>

#define BATCH 16
#define LQ    512
#define LK    4096
#define DM    128

#define TWO_LOG2E 2.8853900817779268f
#define Z_SCALE   1.2751743093739637f

typedef unsigned long long ull;

// ---------------- device scratch (no allocation allowed) ----------------
__device__ __align__(16) __nv_bfloat16 g_qh[(size_t)BATCH * LQ * DM];
__device__ __align__(16) __nv_bfloat16 g_ql[(size_t)BATCH * LQ * DM];
__device__ __align__(16) __nv_bfloat16 g_kh[(size_t)BATCH * LK * DM];
__device__ __align__(16) __nv_bfloat16 g_kl[(size_t)BATCH * LK * DM];
__device__ float    g_rowsum[BATCH * LQ];
__device__ unsigned g_cnt[BATCH * (LQ / 64)];

// ---------------- PTX helpers (baseline sm_80+ features only) ----------------
__device__ __forceinline__ uint32_t smem_u32(const void* p) {
    uint32_t a;
    asm("{ .reg .u64 t; cvta.to.shared.u64 t, %1; cvt.u32.u64 %0, t; }"
        : "=r"(a) : "l"(p));
    return a;
}
__device__ __forceinline__ void cp16(uint32_t dst, const void* src) {
    asm volatile("cp.async.cg.shared.global [%0], [%1], 16;"
                 :: "r"(dst), "l"(src) : "memory");
}
#define CP_COMMIT() asm volatile("cp.async.commit_group;" ::: "memory")
#define CP_WAIT0()  asm volatile("cp.async.wait_group 0;" ::: "memory")

__device__ __forceinline__ void ldsm4(uint32_t& r0, uint32_t& r1,
                                      uint32_t& r2, uint32_t& r3, uint32_t a) {
    asm volatile("ldmatrix.sync.aligned.m8n8.x4.shared.b16 {%0,%1,%2,%3}, [%4];"
                 : "=r"(r0), "=r"(r1), "=r"(r2), "=r"(r3) : "r"(a));
}
__device__ __forceinline__ void mma_bf16(float* d, const uint32_t* a,
                                         const uint32_t* b) {
    asm volatile(
        "mma.sync.aligned.m16n8k16.row.col.f32.bf16.bf16.f32 "
        "{%0,%1,%2,%3}, {%4,%5,%6,%7}, {%8,%9}, {%0,%1,%2,%3};"
        : "+f"(d[0]), "+f"(d[1]), "+f"(d[2]), "+f"(d[3])
        : "r"(a[0]), "r"(a[1]), "r"(a[2]), "r"(a[3]), "r"(b[0]), "r"(b[1]));
}

// ---------------- packed f32x2 math (MUFU-free transcendentals) ----------------
__device__ __forceinline__ ull fma2v(ull a, ull b, ull c) {
    ull d; asm("fma.rn.f32x2 %0, %1, %2, %3;" : "=l"(d) : "l"(a), "l"(b), "l"(c));
    return d;
}
__device__ __forceinline__ ull mul2v(ull a, ull b) {
    ull d; asm("mul.rn.f32x2 %0, %1, %2;" : "=l"(d) : "l"(a), "l"(b)); return d;
}
__device__ __forceinline__ ull add2v(ull a, ull b) {
    ull d; asm("add.rn.f32x2 %0, %1, %2;" : "=l"(d) : "l"(a), "l"(b)); return d;
}
__device__ __forceinline__ float2 unpack2(ull u) {
    float2 f; asm("mov.b64 {%0, %1}, %2;" : "=f"(f.x), "=f"(f.y) : "l"(u)); return f;
}
__device__ __forceinline__ ull pack2(float a, float b) {
    ull u; asm("mov.b64 %0, {%1, %2};" : "=l"(u) : "f"(a), "f"(b)); return u;
}
__device__ __forceinline__ ull make2(float v) {
    unsigned u = __float_as_uint(v);
    return ((ull)u << 32) | (ull)u;
}

__device__ __forceinline__ ull exp2_2(ull y2) {
    ull t2 = add2v(y2, make2(12582912.0f));
    float2 t = unpack2(t2);
    int e0 = (__float_as_int(t.x) - 0x4B400000) << 23;
    int e1 = (__float_as_int(t.y) - 0x4B400000) << 23;
    ull tm2 = add2v(t2, make2(-12582912.0f));
    ull f2  = fma2v(tm2, make2(-1.0f), y2);
    ull p2  = make2(1.3333558146e-3f);
    p2 = fma2v(p2, f2, make2(9.6181291076e-3f));
    p2 = fma2v(p2, f2, make2(5.5504108664e-2f));
    p2 = fma2v(p2, f2, make2(2.4022650696e-1f));
    p2 = fma2v(p2, f2, make2(6.9314718056e-1f));
    p2 = fma2v(p2, f2, make2(1.0f));
    float2 p = unpack2(p2);
    return pack2(__int_as_float(__float_as_int(p.x) + e0),
                 __int_as_float(__float_as_int(p.y) + e1));
}
__device__ __forceinline__ ull rcp2(ull a2) {
    float2 a = unpack2(a2);
    float x0 = __int_as_float(0x7EF311C3 - __float_as_int(a.x));
    float x1 = __int_as_float(0x7EF311C3 - __float_as_int(a.y));
    ull x2  = pack2(x0, x1);
    ull na2 = mul2v(a2, make2(-1.0f));
    ull e2;
    e2 = fma2v(na2, x2, make2(2.0f)); x2 = mul2v(x2, e2);
    e2 = fma2v(na2, x2, make2(2.0f)); x2 = mul2v(x2, e2);
    e2 = fma2v(na2, x2, make2(2.0f)); x2 = mul2v(x2, e2);
    return x2;
}
// exp(C*tanh(s)) for two scores:  tanh(s) = 1 - 2/(1 + 2^{2 log2e s})
__device__ __forceinline__ ull attn_weight2(float s0, float s1) {
    float y0 = fminf(fmaxf(TWO_LOG2E * s0, -30.0f), 30.0f);
    float y1 = fminf(fmaxf(TWO_LOG2E * s1, -30.0f), 30.0f);
    ull u2 = exp2_2(pack2(y0, y1));
    ull r2 = rcp2(add2v(u2, make2(1.0f)));
    ull t2 = fma2v(r2, make2(-2.0f), make2(1.0f));
    return exp2_2(mul2v(t2, make2(Z_SCALE)));
}
__device__ __forceinline__ float fast_rcp(float a) {
    float x = __int_as_float(0x7EF311C3 - __float_as_int(a));
    x = x * fmaf(-a, x, 2.0f);
    x = x * fmaf(-a, x, 2.0f);
    x = x * fmaf(-a, x, 2.0f);
    return x;
}

// ---------------------------------------------------------------------------
// Merged projection, packed f32x2; writes bf16 hi/lo split arrays.
// Last CTA (blockIdx.x == 1152) only zeroes the attn accumulators.
// ---------------------------------------------------------------------------
__global__ __launch_bounds__(256)
void proj_kernel(const float* __restrict__ Q, const float* __restrict__ Wq,
                 const float* __restrict__ bq,
                 const float* __restrict__ K, const float* __restrict__ Wk,
                 const float* __restrict__ bk)
{
    const int tid = threadIdx.x;
    if (blockIdx.x == (BATCH * LQ) / 64 + (BATCH * LK) / 64) {
        for (int i = tid; i < BATCH * LQ; i += 256) g_rowsum[i] = 0.0f;
        if (tid < BATCH * (LQ / 64)) g_cnt[tid] = 0u;
        return;
    }
    const bool is_q = blockIdx.x < (BATCH * LQ) / 64;
    const float* __restrict__ X    = is_q ? Q  : K;
    const float* __restrict__ W    = is_q ? Wq : Wk;
    const float* __restrict__ bias = is_q ? bq : bk;
    __nv_bfloat16* __restrict__ Yh = is_q ? g_qh : g_kh;
    __nv_bfloat16* __restrict__ Yl = is_q ? g_ql : g_kl;
    const int m0 = (is_q ? blockIdx.x : blockIdx.x - (BATCH * LQ) / 64) * 64;

    __shared__ __align__(16) float Xs[64 * 132];

#pragma unroll
    for (int i = 0; i < 8; ++i) {
        int idx = tid + i * 256;
        int m   = idx >> 5;
        int d4  = idx & 31;
        float4 v = *(const float4*)(X + (size_t)(m0 + m) * DM + d4 * 4);
        *(float4*)(Xs + m * 132 + d4 * 4) = v;
    }
    __syncthreads();

    const int tx = tid & 15;
    const int ty = tid >> 4;
    const int c0 = tx * 8;

    ull acc[4][4];
#pragma unroll
    for (int r = 0; r < 4; ++r)
#pragma unroll
        for (int p = 0; p < 4; ++p) acc[r][p] = 0ull;

    for (int d4 = 0; d4 < 32; ++d4) {
        const int d = d4 * 4;
        ulonglong2 wv[4][2];
#pragma unroll
        for (int j = 0; j < 4; ++j) {
            const ulonglong2* wp =
                (const ulonglong2*)(W + (size_t)(d + j) * DM + c0);
            wv[j][0] = wp[0];
            wv[j][1] = wp[1];
        }
#pragma unroll
        for (int r = 0; r < 4; ++r) {
            float4 x4 = *(const float4*)(Xs + (ty * 4 + r) * 132 + d);
            float xv[4] = {x4.x, x4.y, x4.z, x4.w};
#pragma unroll
            for (int j = 0; j < 4; ++j) {
                ull xb = pack2(xv[j], xv[j]);
                acc[r][0] = fma2v(xb, wv[j][0].x, acc[r][0]);
                acc[r][1] = fma2v(xb, wv[j][0].y, acc[r][1]);
                acc[r][2] = fma2v(xb, wv[j][1].x, acc[r][2]);
                acc[r][3] = fma2v(xb, wv[j][1].y, acc[r][3]);
            }
        }
    }

    const ull* bp = (const ull*)(bias + c0);
    ull bb[4] = {bp[0], bp[1], bp[2], bp[3]};
#pragma unroll
    for (int r = 0; r < 4; ++r) {
        size_t row = (size_t)(m0 + ty * 4 + r) * DM;
        union { __nv_bfloat16 h[8]; uint4 v; } uh, ul;
#pragma unroll
        for (int p = 0; p < 4; ++p) {
            float2 a = unpack2(add2v(acc[r][p], bb[p]));
            __nv_bfloat16 h0 = __float2bfloat16_rn(a.x);
            __nv_bfloat16 h1 = __float2bfloat16_rn(a.y);
            uh.h[2 * p]     = h0;
            uh.h[2 * p + 1] = h1;
            ul.h[2 * p]     = __float2bfloat16_rn(a.x - __bfloat162float(h0));
            ul.h[2 * p + 1] = __float2bfloat16_rn(a.y - __bfloat162float(h1));
        }
        *(uint4*)(Yh + row + c0) = uh.v;
        *(uint4*)(Yl + row + c0) = ul.v;
    }
}

// ---------------------------------------------------------------------------
// Attention: mma.sync bf16 3-split. CTA = 64q x 2048k (khalf), 256 threads,
// 2 CTAs/SM (96 KB smem, <=128 regs). 32 k-tiles of 64 tokens, 2-stage
// cp.async pipeline, mask prefetch, global row-sum atomics + 2-CTA handshake,
// in-CTA normalize of own half.
// smem: Q hi @0, Q lo @16384; K bufs @32768 + buf*32768 (hi @+0, lo @+16384).
// A 64-token tile = 64 rows x 16 chunks = 1024 16B chunks -> 4 staging iters
// of 256 threads (R12 bug: only 2 iters staged half the tile).
// Warp tiling: 4 q-warps (16 rows) x 2 k-warps (32 cols).
// ---------------------------------------------------------------------------
#define SMQ   32768
#define KBUF  32768
#define SM_TOTAL (SMQ + 2 * KBUF)   // 98304 bytes

__global__ __launch_bounds__(256, 2)
void attn_kernel(const int* __restrict__ mask, float* __restrict__ out)
{
    extern __shared__ __align__(1024) char smem[];
    const uint32_t su = smem_u32(smem);
    const int tid   = threadIdx.x;
    const int wid   = tid >> 5;
    const int lane  = tid & 31;
    const int khalf = blockIdx.x;          // 0/1
    const int q0    = blockIdx.y * 64;
    const int b     = blockIdx.z;

    const __nv_bfloat16* kh_base =
        g_kh + ((size_t)b * LK + khalf * 2048) * DM;
    const __nv_bfloat16* kl_base =
        g_kl + ((size_t)b * LK + khalf * 2048) * DM;

    // ---- stage Q (64 rows) + K tile 0 (64 tokens = 1024 chunks each) ----
    {
        const __nv_bfloat16* qh = g_qh + ((size_t)b * LQ + q0) * DM;
        const __nv_bfloat16* ql = g_ql + ((size_t)b * LQ + q0) * DM;
#pragma unroll
        for (int i = 0; i < 4; ++i) {
            int idx = tid + i * 256;        // 1024 16B chunks
            int row = idx >> 4, c = idx & 15;
            uint32_t d = (uint32_t)(row * 256 + ((c ^ (row & 7)) << 4));
            cp16(su + d,         qh + idx * 8);
            cp16(su + 16384 + d, ql + idx * 8);
        }
#pragma unroll
        for (int i = 0; i < 4; ++i) {
            int idx = tid + i * 256;        // 1024 chunks (64 tokens)
            int row = idx >> 4, c = idx & 15;
            uint32_t d = (uint32_t)(row * 256 + ((c ^ (row & 7)) << 4));
            cp16(su + SMQ + d,         kh_base + idx * 8);
            cp16(su + SMQ + 16384 + d, kl_base + idx * 8);
        }
        CP_COMMIT();
    }

    // warp tiling: 4 q-warps (16 rows) x 2 k-warps (32 cols)
    const int q_off = (wid >> 1) * 16;
    const int n_off = (wid & 1) * 32;
    const int rsw   = lane & 7;
    const uint32_t aOff = (uint32_t)((q_off + (lane & 15)) * 256);
    const int aSel = (lane >> 4) & 1;
    const uint32_t bOff0 =
        (uint32_t)((n_off + ((lane >> 4) & 1) * 8 + (lane & 7)) * 256);
    const uint32_t bOff1 = bOff0 + 16 * 256;
    const int bSel = (lane >> 3) & 1;
    const int g   = lane >> 2;
    const int tig = lane & 3;

    const size_t rbase = ((size_t)(b * LQ + q0 + q_off + g)) * LK;
    float rs0 = 0.0f, rs1 = 0.0f;

    for (int t = 0; t < 32; ++t) {
        CP_WAIT0();
        __syncthreads();

        // prefetch tile t+1 into the other buffer (overlaps compute of t)
        if (t < 31) {
            const __nv_bfloat16* kh = kh_base + (size_t)(t + 1) * 64 * DM;
            const __nv_bfloat16* kl = kl_base + (size_t)(t + 1) * 64 * DM;
            uint32_t base = su + SMQ + (uint32_t)(((t + 1) & 1) * KBUF);
#pragma unroll
            for (int i = 0; i < 4; ++i) {
                int idx = tid + i * 256;    // full 1024 chunks
                int row = idx >> 4, c = idx & 15;
                uint32_t d = (uint32_t)(row * 256 + ((c ^ (row & 7)) << 4));
                cp16(base + d,         kh + idx * 8);
                cp16(base + 16384 + d, kl + idx * 8);
            }
            CP_COMMIT();
        }

        // prefetch this tile's mask values (overlaps the MMA loop)
        const int nb = khalf * 2048 + t * 64 + n_off + 2 * tig;
        int2 mk[4][2];
#pragma unroll
        for (int j = 0; j < 4; ++j) {
            mk[j][0] = __ldg((const int2*)(mask + rbase + nb + 8 * j));
            mk[j][1] = __ldg((const int2*)(mask + rbase + (size_t)8 * LK
                                           + nb + 8 * j));
        }

        const uint32_t kbuf = su + SMQ + (uint32_t)((t & 1) * KBUF);

        float acc[4][4];
#pragma unroll
        for (int j = 0; j < 4; ++j)
#pragma unroll
            for (int v = 0; v < 4; ++v) acc[j][v] = 0.0f;

#pragma unroll
        for (int dc = 0; dc < 8; ++dc) {
            uint32_t ah[4], al[4], bh[4][2], bl[4][2];
            const uint32_t ca = (uint32_t)(((dc * 2 + aSel) ^ rsw) << 4);
            ldsm4(ah[0], ah[1], ah[2], ah[3], su + aOff + ca);
            ldsm4(al[0], al[1], al[2], al[3], su + 16384 + aOff + ca);
            const uint32_t cb = (uint32_t)(((dc * 2 + bSel) ^ rsw) << 4);
            ldsm4(bh[0][0], bh[0][1], bh[1][0], bh[1][1], kbuf + bOff0 + cb);
            ldsm4(bh[2][0], bh[2][1], bh[3][0], bh[3][1], kbuf + bOff1 + cb);
            ldsm4(bl[0][0], bl[0][1], bl[1][0], bl[1][1],
                  kbuf + 16384 + bOff0 + cb);
            ldsm4(bl[2][0], bl[2][1], bl[3][0], bl[3][1],
                  kbuf + 16384 + bOff1 + cb);
#pragma unroll
            for (int j = 0; j < 4; ++j) {
                mma_bf16(acc[j], ah, bh[j]);   // hi*hi
                mma_bf16(acc[j], ah, bl[j]);   // hi*lo
                mma_bf16(acc[j], al, bh[j]);   // lo*hi
            }
        }

        // ---- epilogue: weights, mask, store e, register row sums ----
#pragma unroll
        for (int j = 0; j < 4; ++j) {
            size_t i0 = rbase + (size_t)(nb + 8 * j);
            size_t i1 = i0 + (size_t)8 * LK;
            float2 w01 = unpack2(attn_weight2(acc[j][0], acc[j][1]));
            float2 w23 = unpack2(attn_weight2(acc[j][2], acc[j][3]));
            float e0 = mk[j][0].x ? w01.x : 0.0f;
            float e1 = mk[j][0].y ? w01.y : 0.0f;
            float e2 = mk[j][1].x ? w23.x : 0.0f;
            float e3 = mk[j][1].y ? w23.y : 0.0f;
            *(float2*)(out + i0) = make_float2(e0, e1);
            *(float2*)(out + i1) = make_float2(e2, e3);
            rs0 += e0 + e1;
            rs1 += e2 + e3;
        }
        __syncthreads();   // all reads of kbuf done before it is restaged
    }

    // ---- row sums: quad-reduce then GLOBAL atomicAdd (cross-CTA) ----
    rs0 += __shfl_xor_sync(0xffffffffu, rs0, 1);
    rs0 += __shfl_xor_sync(0xffffffffu, rs0, 2);
    rs1 += __shfl_xor_sync(0xffffffffu, rs1, 1);
    rs1 += __shfl_xor_sync(0xffffffffu, rs1, 2);
    if (tig == 0) {
        atomicAdd(&g_rowsum[b * LQ + q0 + q_off + g], rs0);
        atomicAdd(&g_rowsum[b * LQ + q0 + q_off + 8 + g], rs1);
    }
    __syncthreads();

    // ---- 2-CTA handshake (adjacent blockIdx.x, co-scheduled) ----
    if (tid == 0) {
        __threadfence();
        const int grp = b * (LQ / 64) + blockIdx.y;
        atomicAdd(&g_cnt[grp], 1u);
        unsigned v;
        do {
            asm volatile("ld.global.acquire.gpu.b32 %0, [%1];"
                         : "=r"(v) : "l"(g_cnt + grp) : "memory");
        } while (v < 2);
    }
    __syncthreads();

    // ---- normalize own half (just-written -> L2-hot) ----
#pragma unroll
    for (int r = 0; r < 8; ++r) {
        int row = wid * 8 + r;
        float inv = fast_rcp(__ldcg(&g_rowsum[b * LQ + q0 + row]));
        float4* rowp = (float4*)(out + ((size_t)(b * LQ) + q0 + row) * LK
                                 + (size_t)khalf * 2048);
#pragma unroll 4
        for (int it = 0; it < 16; ++it) {
            int idx = lane + it * 32;
            float4 v = rowp[idx];
            v.x *= inv; v.y *= inv; v.z *= inv; v.w *= inv;
            rowp[idx] = v;
        }
    }
}

// ---------------------------------------------------------------------------
// launch
// ---------------------------------------------------------------------------
extern "C" void kernel_launch(void* const* d_in, const int* in_sizes, int n_in,
                              void* d_out, int out_size)
{
    (void)in_sizes; (void)n_in; (void)out_size;
    const float* query = (const float*)d_in[0];
    const float* key   = (const float*)d_in[1];
    const int*   mask  = (const int*)  d_in[2];
    const float* Wq    = (const float*)d_in[3];
    const float* bq    = (const float*)d_in[4];
    const float* Wk    = (const float*)d_in[5];
    const float* bk    = (const float*)d_in[6];
    float* out = (float*)d_out;

    cudaFuncSetAttribute(attn_kernel,
                         cudaFuncAttributeMaxDynamicSharedMemorySize, SM_TOTAL);

    // +1 CTA zeroes g_rowsum / g_cnt (replaces the zero_kernel launch)
    proj_kernel<<<(BATCH * LQ) / 64 + (BATCH * LK) / 64 + 1, 256>>>(
        query, Wq, bq, key, Wk, bk);

    dim3 grid(2, LQ / 64, BATCH);
    attn_kernel<<<grid, 256, SM_TOTAL>>>(mask, out);
}

// round 14
// speedup vs baseline: 1.6379x; 1.2982x over previous
#include <cuda_runtime.h>
#include <cuda_bf16.h>
#include <stdint.h>

#define BATCH 16
#define LQ    512
#define LK    4096
#define DM    128

#define TWO_LOG2E 2.8853900817779268f
#define Z_SCALE   1.2751743093739637f

typedef unsigned long long ull;

// ---------------- device scratch (no allocation allowed) ----------------
__device__ __align__(16) __nv_bfloat16 g_qh[(size_t)BATCH * LQ * DM];
__device__ __align__(16) __nv_bfloat16 g_ql[(size_t)BATCH * LQ * DM];
__device__ __align__(16) __nv_bfloat16 g_kh[(size_t)BATCH * LK * DM];
__device__ __align__(16) __nv_bfloat16 g_kl[(size_t)BATCH * LK * DM];
__device__ float    g_rowsum[BATCH * LQ];
__device__ unsigned g_cnt[BATCH * (LQ / 64)];

// ---------------- PTX helpers (baseline sm_80+ features only) ----------------
__device__ __forceinline__ uint32_t smem_u32(const void* p) {
    uint32_t a;
    asm("{ .reg .u64 t; cvta.to.shared.u64 t, %1; cvt.u32.u64 %0, t; }"
        : "=r"(a) : "l"(p));
    return a;
}
__device__ __forceinline__ void cp16(uint32_t dst, const void* src) {
    asm volatile("cp.async.cg.shared.global [%0], [%1], 16;"
                 :: "r"(dst), "l"(src) : "memory");
}
#define CP_COMMIT() asm volatile("cp.async.commit_group;" ::: "memory")
#define CP_WAIT0()  asm volatile("cp.async.wait_group 0;" ::: "memory")

__device__ __forceinline__ void ldsm4(uint32_t& r0, uint32_t& r1,
                                      uint32_t& r2, uint32_t& r3, uint32_t a) {
    asm volatile("ldmatrix.sync.aligned.m8n8.x4.shared.b16 {%0,%1,%2,%3}, [%4];"
                 : "=r"(r0), "=r"(r1), "=r"(r2), "=r"(r3) : "r"(a));
}
__device__ __forceinline__ void ldsm4t(uint32_t& r0, uint32_t& r1,
                                       uint32_t& r2, uint32_t& r3, uint32_t a) {
    asm volatile("ldmatrix.sync.aligned.m8n8.x4.trans.shared.b16 {%0,%1,%2,%3}, [%4];"
                 : "=r"(r0), "=r"(r1), "=r"(r2), "=r"(r3) : "r"(a));
}
__device__ __forceinline__ void mma_bf16(float* d, const uint32_t* a,
                                         const uint32_t* b) {
    asm volatile(
        "mma.sync.aligned.m16n8k16.row.col.f32.bf16.bf16.f32 "
        "{%0,%1,%2,%3}, {%4,%5,%6,%7}, {%8,%9}, {%0,%1,%2,%3};"
        : "+f"(d[0]), "+f"(d[1]), "+f"(d[2]), "+f"(d[3])
        : "r"(a[0]), "r"(a[1]), "r"(a[2]), "r"(a[3]), "r"(b[0]), "r"(b[1]));
}

// ---------------- packed f32x2 math (MUFU-free transcendentals) ----------------
__device__ __forceinline__ ull fma2v(ull a, ull b, ull c) {
    ull d; asm("fma.rn.f32x2 %0, %1, %2, %3;" : "=l"(d) : "l"(a), "l"(b), "l"(c));
    return d;
}
__device__ __forceinline__ ull mul2v(ull a, ull b) {
    ull d; asm("mul.rn.f32x2 %0, %1, %2;" : "=l"(d) : "l"(a), "l"(b)); return d;
}
__device__ __forceinline__ ull add2v(ull a, ull b) {
    ull d; asm("add.rn.f32x2 %0, %1, %2;" : "=l"(d) : "l"(a), "l"(b)); return d;
}
__device__ __forceinline__ float2 unpack2(ull u) {
    float2 f; asm("mov.b64 {%0, %1}, %2;" : "=f"(f.x), "=f"(f.y) : "l"(u)); return f;
}
__device__ __forceinline__ ull pack2(float a, float b) {
    ull u; asm("mov.b64 %0, {%1, %2};" : "=l"(u) : "f"(a), "f"(b)); return u;
}
__device__ __forceinline__ ull make2(float v) {
    unsigned u = __float_as_uint(v);
    return ((ull)u << 32) | (ull)u;
}

__device__ __forceinline__ ull exp2_2(ull y2) {
    ull t2 = add2v(y2, make2(12582912.0f));
    float2 t = unpack2(t2);
    int e0 = (__float_as_int(t.x) - 0x4B400000) << 23;
    int e1 = (__float_as_int(t.y) - 0x4B400000) << 23;
    ull tm2 = add2v(t2, make2(-12582912.0f));
    ull f2  = fma2v(tm2, make2(-1.0f), y2);
    ull p2  = make2(1.3333558146e-3f);
    p2 = fma2v(p2, f2, make2(9.6181291076e-3f));
    p2 = fma2v(p2, f2, make2(5.5504108664e-2f));
    p2 = fma2v(p2, f2, make2(2.4022650696e-1f));
    p2 = fma2v(p2, f2, make2(6.9314718056e-1f));
    p2 = fma2v(p2, f2, make2(1.0f));
    float2 p = unpack2(p2);
    return pack2(__int_as_float(__float_as_int(p.x) + e0),
                 __int_as_float(__float_as_int(p.y) + e1));
}
__device__ __forceinline__ ull rcp2(ull a2) {
    float2 a = unpack2(a2);
    float x0 = __int_as_float(0x7EF311C3 - __float_as_int(a.x));
    float x1 = __int_as_float(0x7EF311C3 - __float_as_int(a.y));
    ull x2  = pack2(x0, x1);
    ull na2 = mul2v(a2, make2(-1.0f));
    ull e2;
    e2 = fma2v(na2, x2, make2(2.0f)); x2 = mul2v(x2, e2);
    e2 = fma2v(na2, x2, make2(2.0f)); x2 = mul2v(x2, e2);
    e2 = fma2v(na2, x2, make2(2.0f)); x2 = mul2v(x2, e2);
    return x2;
}
// exp(C*tanh(s)) for two scores:  tanh(s) = 1 - 2/(1 + 2^{2 log2e s})
__device__ __forceinline__ ull attn_weight2(float s0, float s1) {
    float y0 = fminf(fmaxf(TWO_LOG2E * s0, -30.0f), 30.0f);
    float y1 = fminf(fmaxf(TWO_LOG2E * s1, -30.0f), 30.0f);
    ull u2 = exp2_2(pack2(y0, y1));
    ull r2 = rcp2(add2v(u2, make2(1.0f)));
    ull t2 = fma2v(r2, make2(-2.0f), make2(1.0f));
    return exp2_2(mul2v(t2, make2(Z_SCALE)));
}
__device__ __forceinline__ float fast_rcp(float a) {
    float x = __int_as_float(0x7EF311C3 - __float_as_int(a));
    x = x * fmaf(-a, x, 2.0f);
    x = x * fmaf(-a, x, 2.0f);
    x = x * fmaf(-a, x, 2.0f);
    return x;
}

// convert 8 fp32 -> 8 bf16 hi + 8 bf16 lo (residual)
__device__ __forceinline__ void cvt8(float4 a, float4 b, uint4& uh, uint4& ul) {
    float f[8] = {a.x, a.y, a.z, a.w, b.x, b.y, b.z, b.w};
    union { __nv_bfloat16 h[8]; uint4 v; } H, L;
#pragma unroll
    for (int i = 0; i < 8; ++i) {
        __nv_bfloat16 h = __float2bfloat16_rn(f[i]);
        H.h[i] = h;
        L.h[i] = __float2bfloat16_rn(f[i] - __bfloat162float(h));
    }
    uh = H.v; ul = L.v;
}

// ---------------------------------------------------------------------------
// HMMA projection: Y = X @ W + b via bf16 3-split (Xh*Wh + Xh*Wl + Xl*Wh).
// CTA = 128 rows x N=128 x K=128. X and W converted to bf16 hi/lo in-regs
// during staging. A (X rows) via non-trans ldmatrix (attn-proven layout);
// B (W [d][e], d = reduction) via TRANS ldmatrix: lane t gets
// W[k=2(t%4)][n=t/4] = the m16n8k16 B fragment.
// Warp tile: 32m x 64n (wq = wid&3, wn = wid>>2).
// smem: Xh @0, Xl @32768, Wh @65536, Wl @98304, bias @131072 (132KB).
// Last CTA (blockIdx.x == 576) only zeroes the attn accumulators.
// ---------------------------------------------------------------------------
#define PROJ_CTAS 576              // 73728 rows / 128
#define SM_PROJ   131584

__global__ __launch_bounds__(256)
void proj_kernel(const float* __restrict__ Q, const float* __restrict__ Wq,
                 const float* __restrict__ bq,
                 const float* __restrict__ K, const float* __restrict__ Wk,
                 const float* __restrict__ bk)
{
    const int tid = threadIdx.x;
    if (blockIdx.x == PROJ_CTAS) {
        for (int i = tid; i < BATCH * LQ; i += 256) g_rowsum[i] = 0.0f;
        if (tid < BATCH * (LQ / 64)) g_cnt[tid] = 0u;
        return;
    }
    extern __shared__ __align__(1024) char psm[];
    const uint32_t su = smem_u32(psm);

    const int  m0   = blockIdx.x * 128;
    const bool is_q = m0 < BATCH * LQ;
    const float* __restrict__ X    = is_q ? Q  : K;
    const float* __restrict__ W    = is_q ? Wq : Wk;
    const float* __restrict__ bias = is_q ? bq : bk;
    __nv_bfloat16* __restrict__ Yh = is_q ? g_qh : g_kh;
    __nv_bfloat16* __restrict__ Yl = is_q ? g_ql : g_kl;
    const int ml = is_q ? m0 : m0 - BATCH * LQ;

    // ---- stage bias (fp32) ----
    if (tid < 32)
        *(float4*)(psm + 131072 + tid * 16) = ((const float4*)bias)[tid];

    // ---- stage + split X (128x128) and W (128x128): 2048 16B-chunks each ----
#pragma unroll
    for (int i = 0; i < 8; ++i) {
        int id  = tid + i * 256;
        int row = id >> 4, c = id & 15;
        uint32_t d = (uint32_t)(row * 256 + ((c ^ (row & 7)) << 4));
        const float* xp = X + (size_t)(ml + row) * DM + c * 8;
        uint4 uh, ul;
        cvt8(*(const float4*)xp, *(const float4*)(xp + 4), uh, ul);
        *(uint4*)(psm + d)         = uh;
        *(uint4*)(psm + 32768 + d) = ul;
        const float* wp = W + (size_t)row * DM + c * 8;
        cvt8(*(const float4*)wp, *(const float4*)(wp + 4), uh, ul);
        *(uint4*)(psm + 65536 + d) = uh;
        *(uint4*)(psm + 98304 + d) = ul;
    }
    __syncthreads();

    // ---- warp tiling: wq 0..3 -> 32 m-rows; wn 0..1 -> 64 n-cols ----
    const int wid  = tid >> 5;
    const int lane = tid & 31;
    const int wq   = wid & 3;
    const int wn   = wid >> 2;
    const int rsw  = lane & 7;
    const uint32_t aOff0 = (uint32_t)((wq * 32 + (lane & 15)) * 256);
    const uint32_t aOff1 = aOff0 + 16 * 256;
    const int aSel   = (lane >> 4) & 1;
    const int brow_l = (lane & 7) + 8 * ((lane >> 3) & 1); // k-row within k16
    const int bcsel  = (lane >> 4) & 1;                    // n8-half select

    float acc[2][8][4];
#pragma unroll
    for (int i = 0; i < 2; ++i)
#pragma unroll
        for (int j = 0; j < 8; ++j)
#pragma unroll
            for (int v = 0; v < 4; ++v) acc[i][j][v] = 0.0f;

#pragma unroll
    for (int dc = 0; dc < 8; ++dc) {
        uint32_t ah[2][4], al[2][4], bh[8][2], bl[8][2];
        const uint32_t ca = (uint32_t)(((dc * 2 + aSel) ^ rsw) << 4);
        ldsm4(ah[0][0], ah[0][1], ah[0][2], ah[0][3], su + aOff0 + ca);
        ldsm4(ah[1][0], ah[1][1], ah[1][2], ah[1][3], su + aOff1 + ca);
        ldsm4(al[0][0], al[0][1], al[0][2], al[0][3], su + 32768 + aOff0 + ca);
        ldsm4(al[1][0], al[1][1], al[1][2], al[1][3], su + 32768 + aOff1 + ca);

        const int row_d = dc * 16 + brow_l;
        const uint32_t bb = su + 65536 + (uint32_t)(row_d * 256);
#pragma unroll
        for (int jp = 0; jp < 4; ++jp) {
            uint32_t cc = (uint32_t)(((wn * 8 + 2 * jp + bcsel) ^ rsw) << 4);
            ldsm4t(bh[2 * jp][0], bh[2 * jp][1],
                   bh[2 * jp + 1][0], bh[2 * jp + 1][1], bb + cc);
            ldsm4t(bl[2 * jp][0], bl[2 * jp][1],
                   bl[2 * jp + 1][0], bl[2 * jp + 1][1], bb + 32768 + cc);
        }
#pragma unroll
        for (int i = 0; i < 2; ++i)
#pragma unroll
            for (int j = 0; j < 8; ++j) {
                mma_bf16(acc[i][j], ah[i], bh[j]);   // hi*hi
                mma_bf16(acc[i][j], ah[i], bl[j]);   // hi*lo
                mma_bf16(acc[i][j], al[i], bh[j]);   // lo*hi
            }
    }

    // ---- epilogue: + bias, split to bf16 hi/lo, store ----
    const int g = lane >> 2, tig = lane & 3;
    const float* bias_s = (const float*)(psm + 131072);
#pragma unroll
    for (int i = 0; i < 2; ++i) {
        const int r0 = ml + wq * 32 + i * 16 + g;
#pragma unroll
        for (int j = 0; j < 8; ++j) {
            const int nb = wn * 64 + 8 * j + 2 * tig;
            const float b0 = bias_s[nb], b1 = bias_s[nb + 1];
            float y0 = acc[i][j][0] + b0, y1 = acc[i][j][1] + b1;  // row r0
            float y2 = acc[i][j][2] + b0, y3 = acc[i][j][3] + b1;  // row r0+8
            union { __nv_bfloat16 h[2]; uint32_t u; } p;
            __nv_bfloat16 h0, h1;
            // row r0
            h0 = __float2bfloat16_rn(y0); h1 = __float2bfloat16_rn(y1);
            p.h[0] = h0; p.h[1] = h1;
            *(uint32_t*)(Yh + (size_t)r0 * DM + nb) = p.u;
            p.h[0] = __float2bfloat16_rn(y0 - __bfloat162float(h0));
            p.h[1] = __float2bfloat16_rn(y1 - __bfloat162float(h1));
            *(uint32_t*)(Yl + (size_t)r0 * DM + nb) = p.u;
            // row r0 + 8
            h0 = __float2bfloat16_rn(y2); h1 = __float2bfloat16_rn(y3);
            p.h[0] = h0; p.h[1] = h1;
            *(uint32_t*)(Yh + (size_t)(r0 + 8) * DM + nb) = p.u;
            p.h[0] = __float2bfloat16_rn(y2 - __bfloat162float(h0));
            p.h[1] = __float2bfloat16_rn(y3 - __bfloat162float(h1));
            *(uint32_t*)(Yl + (size_t)(r0 + 8) * DM + nb) = p.u;
        }
    }
}

// ---------------------------------------------------------------------------
// Attention (UNCHANGED from R13): mma.sync bf16 3-split. CTA = 64q x 2048k,
// 256 threads, 2 CTAs/SM. 32 k-tiles of 64 tokens, 2-stage cp.async pipeline,
// mask prefetch, global row-sum atomics + 2-CTA handshake, in-CTA normalize.
// ---------------------------------------------------------------------------
#define SMQ   32768
#define KBUF  32768
#define SM_TOTAL (SMQ + 2 * KBUF)   // 98304 bytes

__global__ __launch_bounds__(256, 2)
void attn_kernel(const int* __restrict__ mask, float* __restrict__ out)
{
    extern __shared__ __align__(1024) char smem[];
    const uint32_t su = smem_u32(smem);
    const int tid   = threadIdx.x;
    const int wid   = tid >> 5;
    const int lane  = tid & 31;
    const int khalf = blockIdx.x;          // 0/1
    const int q0    = blockIdx.y * 64;
    const int b     = blockIdx.z;

    const __nv_bfloat16* kh_base =
        g_kh + ((size_t)b * LK + khalf * 2048) * DM;
    const __nv_bfloat16* kl_base =
        g_kl + ((size_t)b * LK + khalf * 2048) * DM;

    // ---- stage Q (64 rows) + K tile 0 (64 tokens = 1024 chunks each) ----
    {
        const __nv_bfloat16* qh = g_qh + ((size_t)b * LQ + q0) * DM;
        const __nv_bfloat16* ql = g_ql + ((size_t)b * LQ + q0) * DM;
#pragma unroll
        for (int i = 0; i < 4; ++i) {
            int idx = tid + i * 256;
            int row = idx >> 4, c = idx & 15;
            uint32_t d = (uint32_t)(row * 256 + ((c ^ (row & 7)) << 4));
            cp16(su + d,         qh + idx * 8);
            cp16(su + 16384 + d, ql + idx * 8);
        }
#pragma unroll
        for (int i = 0; i < 4; ++i) {
            int idx = tid + i * 256;
            int row = idx >> 4, c = idx & 15;
            uint32_t d = (uint32_t)(row * 256 + ((c ^ (row & 7)) << 4));
            cp16(su + SMQ + d,         kh_base + idx * 8);
            cp16(su + SMQ + 16384 + d, kl_base + idx * 8);
        }
        CP_COMMIT();
    }

    // warp tiling: 4 q-warps (16 rows) x 2 k-warps (32 cols)
    const int q_off = (wid >> 1) * 16;
    const int n_off = (wid & 1) * 32;
    const int rsw   = lane & 7;
    const uint32_t aOff = (uint32_t)((q_off + (lane & 15)) * 256);
    const int aSel = (lane >> 4) & 1;
    const uint32_t bOff0 =
        (uint32_t)((n_off + ((lane >> 4) & 1) * 8 + (lane & 7)) * 256);
    const uint32_t bOff1 = bOff0 + 16 * 256;
    const int bSel = (lane >> 3) & 1;
    const int g   = lane >> 2;
    const int tig = lane & 3;

    const size_t rbase = ((size_t)(b * LQ + q0 + q_off + g)) * LK;
    float rs0 = 0.0f, rs1 = 0.0f;

    for (int t = 0; t < 32; ++t) {
        CP_WAIT0();
        __syncthreads();

        if (t < 31) {
            const __nv_bfloat16* kh = kh_base + (size_t)(t + 1) * 64 * DM;
            const __nv_bfloat16* kl = kl_base + (size_t)(t + 1) * 64 * DM;
            uint32_t base = su + SMQ + (uint32_t)(((t + 1) & 1) * KBUF);
#pragma unroll
            for (int i = 0; i < 4; ++i) {
                int idx = tid + i * 256;
                int row = idx >> 4, c = idx & 15;
                uint32_t d = (uint32_t)(row * 256 + ((c ^ (row & 7)) << 4));
                cp16(base + d,         kh + idx * 8);
                cp16(base + 16384 + d, kl + idx * 8);
            }
            CP_COMMIT();
        }

        const int nb = khalf * 2048 + t * 64 + n_off + 2 * tig;
        int2 mk[4][2];
#pragma unroll
        for (int j = 0; j < 4; ++j) {
            mk[j][0] = __ldg((const int2*)(mask + rbase + nb + 8 * j));
            mk[j][1] = __ldg((const int2*)(mask + rbase + (size_t)8 * LK
                                           + nb + 8 * j));
        }

        const uint32_t kbuf = su + SMQ + (uint32_t)((t & 1) * KBUF);

        float acc[4][4];
#pragma unroll
        for (int j = 0; j < 4; ++j)
#pragma unroll
            for (int v = 0; v < 4; ++v) acc[j][v] = 0.0f;

#pragma unroll
        for (int dc = 0; dc < 8; ++dc) {
            uint32_t ah[4], al[4], bh[4][2], bl[4][2];
            const uint32_t ca = (uint32_t)(((dc * 2 + aSel) ^ rsw) << 4);
            ldsm4(ah[0], ah[1], ah[2], ah[3], su + aOff + ca);
            ldsm4(al[0], al[1], al[2], al[3], su + 16384 + aOff + ca);
            const uint32_t cb = (uint32_t)(((dc * 2 + bSel) ^ rsw) << 4);
            ldsm4(bh[0][0], bh[0][1], bh[1][0], bh[1][1], kbuf + bOff0 + cb);
            ldsm4(bh[2][0], bh[2][1], bh[3][0], bh[3][1], kbuf + bOff1 + cb);
            ldsm4(bl[0][0], bl[0][1], bl[1][0], bl[1][1],
                  kbuf + 16384 + bOff0 + cb);
            ldsm4(bl[2][0], bl[2][1], bl[3][0], bl[3][1],
                  kbuf + 16384 + bOff1 + cb);
#pragma unroll
            for (int j = 0; j < 4; ++j) {
                mma_bf16(acc[j], ah, bh[j]);
                mma_bf16(acc[j], ah, bl[j]);
                mma_bf16(acc[j], al, bh[j]);
            }
        }

#pragma unroll
        for (int j = 0; j < 4; ++j) {
            size_t i0 = rbase + (size_t)(nb + 8 * j);
            size_t i1 = i0 + (size_t)8 * LK;
            float2 w01 = unpack2(attn_weight2(acc[j][0], acc[j][1]));
            float2 w23 = unpack2(attn_weight2(acc[j][2], acc[j][3]));
            float e0 = mk[j][0].x ? w01.x : 0.0f;
            float e1 = mk[j][0].y ? w01.y : 0.0f;
            float e2 = mk[j][1].x ? w23.x : 0.0f;
            float e3 = mk[j][1].y ? w23.y : 0.0f;
            *(float2*)(out + i0) = make_float2(e0, e1);
            *(float2*)(out + i1) = make_float2(e2, e3);
            rs0 += e0 + e1;
            rs1 += e2 + e3;
        }
        __syncthreads();
    }

    rs0 += __shfl_xor_sync(0xffffffffu, rs0, 1);
    rs0 += __shfl_xor_sync(0xffffffffu, rs0, 2);
    rs1 += __shfl_xor_sync(0xffffffffu, rs1, 1);
    rs1 += __shfl_xor_sync(0xffffffffu, rs1, 2);
    if (tig == 0) {
        atomicAdd(&g_rowsum[b * LQ + q0 + q_off + g], rs0);
        atomicAdd(&g_rowsum[b * LQ + q0 + q_off + 8 + g], rs1);
    }
    __syncthreads();

    if (tid == 0) {
        __threadfence();
        const int grp = b * (LQ / 64) + blockIdx.y;
        atomicAdd(&g_cnt[grp], 1u);
        unsigned v;
        do {
            asm volatile("ld.global.acquire.gpu.b32 %0, [%1];"
                         : "=r"(v) : "l"(g_cnt + grp) : "memory");
        } while (v < 2);
    }
    __syncthreads();

#pragma unroll
    for (int r = 0; r < 8; ++r) {
        int row = wid * 8 + r;
        float inv = fast_rcp(__ldcg(&g_rowsum[b * LQ + q0 + row]));
        float4* rowp = (float4*)(out + ((size_t)(b * LQ) + q0 + row) * LK
                                 + (size_t)khalf * 2048);
#pragma unroll 4
        for (int it = 0; it < 16; ++it) {
            int idx = lane + it * 32;
            float4 v = rowp[idx];
            v.x *= inv; v.y *= inv; v.z *= inv; v.w *= inv;
            rowp[idx] = v;
        }
    }
}

// ---------------------------------------------------------------------------
// launch
// ---------------------------------------------------------------------------
extern "C" void kernel_launch(void* const* d_in, const int* in_sizes, int n_in,
                              void* d_out, int out_size)
{
    (void)in_sizes; (void)n_in; (void)out_size;
    const float* query = (const float*)d_in[0];
    const float* key   = (const float*)d_in[1];
    const int*   mask  = (const int*)  d_in[2];
    const float* Wq    = (const float*)d_in[3];
    const float* bq    = (const float*)d_in[4];
    const float* Wk    = (const float*)d_in[5];
    const float* bk    = (const float*)d_in[6];
    float* out = (float*)d_out;

    cudaFuncSetAttribute(proj_kernel,
                         cudaFuncAttributeMaxDynamicSharedMemorySize, SM_PROJ);
    cudaFuncSetAttribute(attn_kernel,
                         cudaFuncAttributeMaxDynamicSharedMemorySize, SM_TOTAL);

    proj_kernel<<<PROJ_CTAS + 1, 256, SM_PROJ>>>(query, Wq, bq, key, Wk, bk);

    dim3 grid(2, LQ / 64, BATCH);
    attn_kernel<<<grid, 256, SM_TOTAL>>>(mask, out);
}

// round 15
// speedup vs baseline: 1.6404x; 1.0015x over previous
#include <cuda_runtime.h>
#include <cuda_bf16.h>
#include <stdint.h>

#define BATCH 16
#define LQ    512
#define LK    4096
#define DM    128

#define TWO_LOG2E 2.8853900817779268f
#define Z_SCALE   1.2751743093739637f

typedef unsigned long long ull;

// ---------------- device scratch (no allocation allowed) ----------------
__device__ __align__(16) __nv_bfloat16 g_qh[(size_t)BATCH * LQ * DM];
__device__ __align__(16) __nv_bfloat16 g_ql[(size_t)BATCH * LQ * DM];
__device__ __align__(16) __nv_bfloat16 g_kh[(size_t)BATCH * LK * DM];
__device__ __align__(16) __nv_bfloat16 g_kl[(size_t)BATCH * LK * DM];
__device__ float    g_rowsum[BATCH * LQ];
__device__ unsigned g_cnt[BATCH * (LQ / 64)];

// ---------------- PTX helpers (baseline sm_80+ features only) ----------------
__device__ __forceinline__ uint32_t smem_u32(const void* p) {
    uint32_t a;
    asm("{ .reg .u64 t; cvta.to.shared.u64 t, %1; cvt.u32.u64 %0, t; }"
        : "=r"(a) : "l"(p));
    return a;
}
__device__ __forceinline__ void cp16(uint32_t dst, const void* src) {
    asm volatile("cp.async.cg.shared.global [%0], [%1], 16;"
                 :: "r"(dst), "l"(src) : "memory");
}
#define CP_COMMIT() asm volatile("cp.async.commit_group;" ::: "memory")
#define CP_WAIT0()  asm volatile("cp.async.wait_group 0;" ::: "memory")

__device__ __forceinline__ void ldsm4(uint32_t& r0, uint32_t& r1,
                                      uint32_t& r2, uint32_t& r3, uint32_t a) {
    asm volatile("ldmatrix.sync.aligned.m8n8.x4.shared.b16 {%0,%1,%2,%3}, [%4];"
                 : "=r"(r0), "=r"(r1), "=r"(r2), "=r"(r3) : "r"(a));
}
__device__ __forceinline__ void ldsm4t(uint32_t& r0, uint32_t& r1,
                                       uint32_t& r2, uint32_t& r3, uint32_t a) {
    asm volatile("ldmatrix.sync.aligned.m8n8.x4.trans.shared.b16 {%0,%1,%2,%3}, [%4];"
                 : "=r"(r0), "=r"(r1), "=r"(r2), "=r"(r3) : "r"(a));
}
__device__ __forceinline__ void mma_bf16(float* d, const uint32_t* a,
                                         const uint32_t* b) {
    asm volatile(
        "mma.sync.aligned.m16n8k16.row.col.f32.bf16.bf16.f32 "
        "{%0,%1,%2,%3}, {%4,%5,%6,%7}, {%8,%9}, {%0,%1,%2,%3};"
        : "+f"(d[0]), "+f"(d[1]), "+f"(d[2]), "+f"(d[3])
        : "r"(a[0]), "r"(a[1]), "r"(a[2]), "r"(a[3]), "r"(b[0]), "r"(b[1]));
}

// ---------------- packed f32x2 math (MUFU-free transcendentals) ----------------
__device__ __forceinline__ ull fma2v(ull a, ull b, ull c) {
    ull d; asm("fma.rn.f32x2 %0, %1, %2, %3;" : "=l"(d) : "l"(a), "l"(b), "l"(c));
    return d;
}
__device__ __forceinline__ ull mul2v(ull a, ull b) {
    ull d; asm("mul.rn.f32x2 %0, %1, %2;" : "=l"(d) : "l"(a), "l"(b)); return d;
}
__device__ __forceinline__ ull add2v(ull a, ull b) {
    ull d; asm("add.rn.f32x2 %0, %1, %2;" : "=l"(d) : "l"(a), "l"(b)); return d;
}
__device__ __forceinline__ float2 unpack2(ull u) {
    float2 f; asm("mov.b64 {%0, %1}, %2;" : "=f"(f.x), "=f"(f.y) : "l"(u)); return f;
}
__device__ __forceinline__ ull pack2(float a, float b) {
    ull u; asm("mov.b64 %0, {%1, %2};" : "=l"(u) : "f"(a), "f"(b)); return u;
}
__device__ __forceinline__ ull make2(float v) {
    unsigned u = __float_as_uint(v);
    return ((ull)u << 32) | (ull)u;
}

__device__ __forceinline__ ull exp2_2(ull y2) {
    ull t2 = add2v(y2, make2(12582912.0f));
    float2 t = unpack2(t2);
    int e0 = (__float_as_int(t.x) - 0x4B400000) << 23;
    int e1 = (__float_as_int(t.y) - 0x4B400000) << 23;
    ull tm2 = add2v(t2, make2(-12582912.0f));
    ull f2  = fma2v(tm2, make2(-1.0f), y2);
    ull p2  = make2(1.3333558146e-3f);
    p2 = fma2v(p2, f2, make2(9.6181291076e-3f));
    p2 = fma2v(p2, f2, make2(5.5504108664e-2f));
    p2 = fma2v(p2, f2, make2(2.4022650696e-1f));
    p2 = fma2v(p2, f2, make2(6.9314718056e-1f));
    p2 = fma2v(p2, f2, make2(1.0f));
    float2 p = unpack2(p2);
    return pack2(__int_as_float(__float_as_int(p.x) + e0),
                 __int_as_float(__float_as_int(p.y) + e1));
}
__device__ __forceinline__ ull rcp2(ull a2) {
    float2 a = unpack2(a2);
    float x0 = __int_as_float(0x7EF311C3 - __float_as_int(a.x));
    float x1 = __int_as_float(0x7EF311C3 - __float_as_int(a.y));
    ull x2  = pack2(x0, x1);
    ull na2 = mul2v(a2, make2(-1.0f));
    ull e2;
    e2 = fma2v(na2, x2, make2(2.0f)); x2 = mul2v(x2, e2);
    e2 = fma2v(na2, x2, make2(2.0f)); x2 = mul2v(x2, e2);
    e2 = fma2v(na2, x2, make2(2.0f)); x2 = mul2v(x2, e2);
    return x2;
}
// exp(C*tanh(s)) for two scores:  tanh(s) = 1 - 2/(1 + 2^{2 log2e s})
__device__ __forceinline__ ull attn_weight2(float s0, float s1) {
    float y0 = fminf(fmaxf(TWO_LOG2E * s0, -30.0f), 30.0f);
    float y1 = fminf(fmaxf(TWO_LOG2E * s1, -30.0f), 30.0f);
    ull u2 = exp2_2(pack2(y0, y1));
    ull r2 = rcp2(add2v(u2, make2(1.0f)));
    ull t2 = fma2v(r2, make2(-2.0f), make2(1.0f));
    return exp2_2(mul2v(t2, make2(Z_SCALE)));
}
__device__ __forceinline__ float fast_rcp(float a) {
    float x = __int_as_float(0x7EF311C3 - __float_as_int(a));
    x = x * fmaf(-a, x, 2.0f);
    x = x * fmaf(-a, x, 2.0f);
    x = x * fmaf(-a, x, 2.0f);
    return x;
}

// convert 8 fp32 -> 8 bf16 hi + 8 bf16 lo (residual)
__device__ __forceinline__ void cvt8(float4 a, float4 b, uint4& uh, uint4& ul) {
    float f[8] = {a.x, a.y, a.z, a.w, b.x, b.y, b.z, b.w};
    union { __nv_bfloat16 h[8]; uint4 v; } H, L;
#pragma unroll
    for (int i = 0; i < 8; ++i) {
        __nv_bfloat16 h = __float2bfloat16_rn(f[i]);
        H.h[i] = h;
        L.h[i] = __float2bfloat16_rn(f[i] - __bfloat162float(h));
    }
    uh = H.v; ul = L.v;
}

// ---------------------------------------------------------------------------
// HMMA projection (UNCHANGED from R14): Y = X @ W + b via bf16 3-split.
// Last CTA (blockIdx.x == 576) only zeroes the attn accumulators.
// ---------------------------------------------------------------------------
#define PROJ_CTAS 576              // 73728 rows / 128
#define SM_PROJ   131584

__global__ __launch_bounds__(256)
void proj_kernel(const float* __restrict__ Q, const float* __restrict__ Wq,
                 const float* __restrict__ bq,
                 const float* __restrict__ K, const float* __restrict__ Wk,
                 const float* __restrict__ bk)
{
    const int tid = threadIdx.x;
    if (blockIdx.x == PROJ_CTAS) {
        for (int i = tid; i < BATCH * LQ; i += 256) g_rowsum[i] = 0.0f;
        if (tid < BATCH * (LQ / 64)) g_cnt[tid] = 0u;
        return;
    }
    extern __shared__ __align__(1024) char psm[];
    const uint32_t su = smem_u32(psm);

    const int  m0   = blockIdx.x * 128;
    const bool is_q = m0 < BATCH * LQ;
    const float* __restrict__ X    = is_q ? Q  : K;
    const float* __restrict__ W    = is_q ? Wq : Wk;
    const float* __restrict__ bias = is_q ? bq : bk;
    __nv_bfloat16* __restrict__ Yh = is_q ? g_qh : g_kh;
    __nv_bfloat16* __restrict__ Yl = is_q ? g_ql : g_kl;
    const int ml = is_q ? m0 : m0 - BATCH * LQ;

    if (tid < 32)
        *(float4*)(psm + 131072 + tid * 16) = ((const float4*)bias)[tid];

#pragma unroll
    for (int i = 0; i < 8; ++i) {
        int id  = tid + i * 256;
        int row = id >> 4, c = id & 15;
        uint32_t d = (uint32_t)(row * 256 + ((c ^ (row & 7)) << 4));
        const float* xp = X + (size_t)(ml + row) * DM + c * 8;
        uint4 uh, ul;
        cvt8(*(const float4*)xp, *(const float4*)(xp + 4), uh, ul);
        *(uint4*)(psm + d)         = uh;
        *(uint4*)(psm + 32768 + d) = ul;
        const float* wp = W + (size_t)row * DM + c * 8;
        cvt8(*(const float4*)wp, *(const float4*)(wp + 4), uh, ul);
        *(uint4*)(psm + 65536 + d) = uh;
        *(uint4*)(psm + 98304 + d) = ul;
    }
    __syncthreads();

    const int wid  = tid >> 5;
    const int lane = tid & 31;
    const int wq   = wid & 3;
    const int wn   = wid >> 2;
    const int rsw  = lane & 7;
    const uint32_t aOff0 = (uint32_t)((wq * 32 + (lane & 15)) * 256);
    const uint32_t aOff1 = aOff0 + 16 * 256;
    const int aSel   = (lane >> 4) & 1;
    const int brow_l = (lane & 7) + 8 * ((lane >> 3) & 1);
    const int bcsel  = (lane >> 4) & 1;

    float acc[2][8][4];
#pragma unroll
    for (int i = 0; i < 2; ++i)
#pragma unroll
        for (int j = 0; j < 8; ++j)
#pragma unroll
            for (int v = 0; v < 4; ++v) acc[i][j][v] = 0.0f;

#pragma unroll
    for (int dc = 0; dc < 8; ++dc) {
        uint32_t ah[2][4], al[2][4], bh[8][2], bl[8][2];
        const uint32_t ca = (uint32_t)(((dc * 2 + aSel) ^ rsw) << 4);
        ldsm4(ah[0][0], ah[0][1], ah[0][2], ah[0][3], su + aOff0 + ca);
        ldsm4(ah[1][0], ah[1][1], ah[1][2], ah[1][3], su + aOff1 + ca);
        ldsm4(al[0][0], al[0][1], al[0][2], al[0][3], su + 32768 + aOff0 + ca);
        ldsm4(al[1][0], al[1][1], al[1][2], al[1][3], su + 32768 + aOff1 + ca);

        const int row_d = dc * 16 + brow_l;
        const uint32_t bb = su + 65536 + (uint32_t)(row_d * 256);
#pragma unroll
        for (int jp = 0; jp < 4; ++jp) {
            uint32_t cc = (uint32_t)(((wn * 8 + 2 * jp + bcsel) ^ rsw) << 4);
            ldsm4t(bh[2 * jp][0], bh[2 * jp][1],
                   bh[2 * jp + 1][0], bh[2 * jp + 1][1], bb + cc);
            ldsm4t(bl[2 * jp][0], bl[2 * jp][1],
                   bl[2 * jp + 1][0], bl[2 * jp + 1][1], bb + 32768 + cc);
        }
#pragma unroll
        for (int i = 0; i < 2; ++i)
#pragma unroll
            for (int j = 0; j < 8; ++j) {
                mma_bf16(acc[i][j], ah[i], bh[j]);
                mma_bf16(acc[i][j], ah[i], bl[j]);
                mma_bf16(acc[i][j], al[i], bh[j]);
            }
    }

    const int g = lane >> 2, tig = lane & 3;
    const float* bias_s = (const float*)(psm + 131072);
#pragma unroll
    for (int i = 0; i < 2; ++i) {
        const int r0 = ml + wq * 32 + i * 16 + g;
#pragma unroll
        for (int j = 0; j < 8; ++j) {
            const int nb = wn * 64 + 8 * j + 2 * tig;
            const float b0 = bias_s[nb], b1 = bias_s[nb + 1];
            float y0 = acc[i][j][0] + b0, y1 = acc[i][j][1] + b1;
            float y2 = acc[i][j][2] + b0, y3 = acc[i][j][3] + b1;
            union { __nv_bfloat16 h[2]; uint32_t u; } p;
            __nv_bfloat16 h0, h1;
            h0 = __float2bfloat16_rn(y0); h1 = __float2bfloat16_rn(y1);
            p.h[0] = h0; p.h[1] = h1;
            *(uint32_t*)(Yh + (size_t)r0 * DM + nb) = p.u;
            p.h[0] = __float2bfloat16_rn(y0 - __bfloat162float(h0));
            p.h[1] = __float2bfloat16_rn(y1 - __bfloat162float(h1));
            *(uint32_t*)(Yl + (size_t)r0 * DM + nb) = p.u;
            h0 = __float2bfloat16_rn(y2); h1 = __float2bfloat16_rn(y3);
            p.h[0] = h0; p.h[1] = h1;
            *(uint32_t*)(Yh + (size_t)(r0 + 8) * DM + nb) = p.u;
            p.h[0] = __float2bfloat16_rn(y2 - __bfloat162float(h0));
            p.h[1] = __float2bfloat16_rn(y3 - __bfloat162float(h1));
            *(uint32_t*)(Yl + (size_t)(r0 + 8) * DM + nb) = p.u;
        }
    }
}

// ---------------------------------------------------------------------------
// Attention: mma.sync bf16 3-split. CTA = 64q x 2048k (khalf), 256 threads,
// 2 CTAs/SM. 32 k-tiles of 64 tokens, 2-stage cp.async pipeline.
// R15 latency fixes vs R13/R14:
//   - mask LDGs issued BEFORE CP_WAIT0 (latency overlaps wait+barrier)
//   - single __syncthreads per tile (bottom barrier was redundant: the next
//     iteration's top barrier already orders LDSM reads vs cp.async refill)
//   - fragment ping-pong across dc: load dc+1's LDSM fragments while dc's
//     12 HMMAs issue; MMAs grouped 4xhh, 4xhl, 4xlh for 4-wide ILP
// ---------------------------------------------------------------------------
#define SMQ   32768
#define KBUF  32768
#define SM_TOTAL (SMQ + 2 * KBUF)   // 98304 bytes

__global__ __launch_bounds__(256, 2)
void attn_kernel(const int* __restrict__ mask, float* __restrict__ out)
{
    extern __shared__ __align__(1024) char smem[];
    const uint32_t su = smem_u32(smem);
    const int tid   = threadIdx.x;
    const int wid   = tid >> 5;
    const int lane  = tid & 31;
    const int khalf = blockIdx.x;          // 0/1
    const int q0    = blockIdx.y * 64;
    const int b     = blockIdx.z;

    const __nv_bfloat16* kh_base =
        g_kh + ((size_t)b * LK + khalf * 2048) * DM;
    const __nv_bfloat16* kl_base =
        g_kl + ((size_t)b * LK + khalf * 2048) * DM;

    // ---- stage Q (64 rows) + K tile 0 (64 tokens = 1024 chunks each) ----
    {
        const __nv_bfloat16* qh = g_qh + ((size_t)b * LQ + q0) * DM;
        const __nv_bfloat16* ql = g_ql + ((size_t)b * LQ + q0) * DM;
#pragma unroll
        for (int i = 0; i < 4; ++i) {
            int idx = tid + i * 256;
            int row = idx >> 4, c = idx & 15;
            uint32_t d = (uint32_t)(row * 256 + ((c ^ (row & 7)) << 4));
            cp16(su + d,         qh + idx * 8);
            cp16(su + 16384 + d, ql + idx * 8);
        }
#pragma unroll
        for (int i = 0; i < 4; ++i) {
            int idx = tid + i * 256;
            int row = idx >> 4, c = idx & 15;
            uint32_t d = (uint32_t)(row * 256 + ((c ^ (row & 7)) << 4));
            cp16(su + SMQ + d,         kh_base + idx * 8);
            cp16(su + SMQ + 16384 + d, kl_base + idx * 8);
        }
        CP_COMMIT();
    }

    // warp tiling: 4 q-warps (16 rows) x 2 k-warps (32 cols)
    const int q_off = (wid >> 1) * 16;
    const int n_off = (wid & 1) * 32;
    const int rsw   = lane & 7;
    const uint32_t aOff = (uint32_t)((q_off + (lane & 15)) * 256);
    const int aSel = (lane >> 4) & 1;
    const uint32_t bOff0 =
        (uint32_t)((n_off + ((lane >> 4) & 1) * 8 + (lane & 7)) * 256);
    const uint32_t bOff1 = bOff0 + 16 * 256;
    const int bSel = (lane >> 3) & 1;
    const int g   = lane >> 2;
    const int tig = lane & 3;

    const size_t rbase = ((size_t)(b * LQ + q0 + q_off + g)) * LK;
    float rs0 = 0.0f, rs1 = 0.0f;

// fragment loader: stage s <- frags for chunk dc of the current k buffer
#define LOADFRAG(dc_, s_)                                                     \
    do {                                                                      \
        const uint32_t ca_ = (uint32_t)((((dc_) * 2 + aSel) ^ rsw) << 4);     \
        ldsm4(ah[s_][0], ah[s_][1], ah[s_][2], ah[s_][3], su + aOff + ca_);   \
        ldsm4(al[s_][0], al[s_][1], al[s_][2], al[s_][3],                     \
              su + 16384 + aOff + ca_);                                       \
        const uint32_t cb_ = (uint32_t)((((dc_) * 2 + bSel) ^ rsw) << 4);     \
        ldsm4(bh[s_][0][0], bh[s_][0][1], bh[s_][1][0], bh[s_][1][1],         \
              kbuf + bOff0 + cb_);                                            \
        ldsm4(bh[s_][2][0], bh[s_][2][1], bh[s_][3][0], bh[s_][3][1],         \
              kbuf + bOff1 + cb_);                                            \
        ldsm4(bl[s_][0][0], bl[s_][0][1], bl[s_][1][0], bl[s_][1][1],         \
              kbuf + 16384 + bOff0 + cb_);                                    \
        ldsm4(bl[s_][2][0], bl[s_][2][1], bl[s_][3][0], bl[s_][3][1],         \
              kbuf + 16384 + bOff1 + cb_);                                    \
    } while (0)

    for (int t = 0; t < 32; ++t) {
        // mask loads first: no smem dependence, latency hides under wait+bar
        const int nb = khalf * 2048 + t * 64 + n_off + 2 * tig;
        int2 mk[4][2];
#pragma unroll
        for (int j = 0; j < 4; ++j) {
            mk[j][0] = __ldg((const int2*)(mask + rbase + nb + 8 * j));
            mk[j][1] = __ldg((const int2*)(mask + rbase + (size_t)8 * LK
                                           + nb + 8 * j));
        }

        CP_WAIT0();
        __syncthreads();   // sole barrier: staging visible + prior LDSM done

        // prefetch tile t+1 into the other buffer (overlaps compute of t)
        if (t < 31) {
            const __nv_bfloat16* kh = kh_base + (size_t)(t + 1) * 64 * DM;
            const __nv_bfloat16* kl = kl_base + (size_t)(t + 1) * 64 * DM;
            uint32_t base = su + SMQ + (uint32_t)(((t + 1) & 1) * KBUF);
#pragma unroll
            for (int i = 0; i < 4; ++i) {
                int idx = tid + i * 256;
                int row = idx >> 4, c = idx & 15;
                uint32_t d = (uint32_t)(row * 256 + ((c ^ (row & 7)) << 4));
                cp16(base + d,         kh + idx * 8);
                cp16(base + 16384 + d, kl + idx * 8);
            }
            CP_COMMIT();
        }

        const uint32_t kbuf = su + SMQ + (uint32_t)((t & 1) * KBUF);

        float acc[4][4];
#pragma unroll
        for (int j = 0; j < 4; ++j)
#pragma unroll
            for (int v = 0; v < 4; ++v) acc[j][v] = 0.0f;

        // fragment ping-pong: load dc+1 while dc's MMAs issue
        uint32_t ah[2][4], al[2][4], bh[2][4][2], bl[2][4][2];
        LOADFRAG(0, 0);
#pragma unroll
        for (int dc = 0; dc < 8; ++dc) {
            const int s = dc & 1;
            if (dc < 7) LOADFRAG(dc + 1, s ^ 1);
#pragma unroll
            for (int j = 0; j < 4; ++j) mma_bf16(acc[j], ah[s], bh[s][j]);
#pragma unroll
            for (int j = 0; j < 4; ++j) mma_bf16(acc[j], ah[s], bl[s][j]);
#pragma unroll
            for (int j = 0; j < 4; ++j) mma_bf16(acc[j], al[s], bh[s][j]);
        }

        // ---- epilogue: weights, mask, store e, register row sums ----
#pragma unroll
        for (int j = 0; j < 4; ++j) {
            size_t i0 = rbase + (size_t)(nb + 8 * j);
            size_t i1 = i0 + (size_t)8 * LK;
            float2 w01 = unpack2(attn_weight2(acc[j][0], acc[j][1]));
            float2 w23 = unpack2(attn_weight2(acc[j][2], acc[j][3]));
            float e0 = mk[j][0].x ? w01.x : 0.0f;
            float e1 = mk[j][0].y ? w01.y : 0.0f;
            float e2 = mk[j][1].x ? w23.x : 0.0f;
            float e3 = mk[j][1].y ? w23.y : 0.0f;
            *(float2*)(out + i0) = make_float2(e0, e1);
            *(float2*)(out + i1) = make_float2(e2, e3);
            rs0 += e0 + e1;
            rs1 += e2 + e3;
        }
    }
#undef LOADFRAG

    // ---- row sums: quad-reduce then GLOBAL atomicAdd (cross-CTA) ----
    rs0 += __shfl_xor_sync(0xffffffffu, rs0, 1);
    rs0 += __shfl_xor_sync(0xffffffffu, rs0, 2);
    rs1 += __shfl_xor_sync(0xffffffffu, rs1, 1);
    rs1 += __shfl_xor_sync(0xffffffffu, rs1, 2);
    if (tig == 0) {
        atomicAdd(&g_rowsum[b * LQ + q0 + q_off + g], rs0);
        atomicAdd(&g_rowsum[b * LQ + q0 + q_off + 8 + g], rs1);
    }
    __syncthreads();

    // ---- 2-CTA handshake (adjacent blockIdx.x, co-scheduled) ----
    if (tid == 0) {
        __threadfence();
        const int grp = b * (LQ / 64) + blockIdx.y;
        atomicAdd(&g_cnt[grp], 1u);
        unsigned v;
        do {
            asm volatile("ld.global.acquire.gpu.b32 %0, [%1];"
                         : "=r"(v) : "l"(g_cnt + grp) : "memory");
        } while (v < 2);
    }
    __syncthreads();

    // ---- normalize own half ----
#pragma unroll
    for (int r = 0; r < 8; ++r) {
        int row = wid * 8 + r;
        float inv = fast_rcp(__ldcg(&g_rowsum[b * LQ + q0 + row]));
        float4* rowp = (float4*)(out + ((size_t)(b * LQ) + q0 + row) * LK
                                 + (size_t)khalf * 2048);
#pragma unroll 4
        for (int it = 0; it < 16; ++it) {
            int idx = lane + it * 32;
            float4 v = rowp[idx];
            v.x *= inv; v.y *= inv; v.z *= inv; v.w *= inv;
            rowp[idx] = v;
        }
    }
}

// ---------------------------------------------------------------------------
// launch
// ---------------------------------------------------------------------------
extern "C" void kernel_launch(void* const* d_in, const int* in_sizes, int n_in,
                              void* d_out, int out_size)
{
    (void)in_sizes; (void)n_in; (void)out_size;
    const float* query = (const float*)d_in[0];
    const float* key   = (const float*)d_in[1];
    const int*   mask  = (const int*)  d_in[2];
    const float* Wq    = (const float*)d_in[3];
    const float* bq    = (const float*)d_in[4];
    const float* Wk    = (const float*)d_in[5];
    const float* bk    = (const float*)d_in[6];
    float* out = (float*)d_out;

    cudaFuncSetAttribute(proj_kernel,
                         cudaFuncAttributeMaxDynamicSharedMemorySize, SM_PROJ);
    cudaFuncSetAttribute(attn_kernel,
                         cudaFuncAttributeMaxDynamicSharedMemorySize, SM_TOTAL);

    proj_kernel<<<PROJ_CTAS + 1, 256, SM_PROJ>>>(query, Wq, bq, key, Wk, bk);

    dim3 grid(2, LQ / 64, BATCH);
    attn_kernel<<<grid, 256, SM_TOTAL>>>(mask, out);
}